// round 5
// baseline (speedup 1.0000x reference)
#include <cuda_runtime.h>
#include <cuda_bf16.h>
#include <cstdint>

// ---------------------------------------------------------------------------
// Problem constants
// ---------------------------------------------------------------------------
constexpr int CCH   = 66;
constexpr int TLEN  = 96;
constexpr int BSZ   = 2048;
constexpr int FIN   = 9 * CCH * 12;   // 7128
constexpr int HID   = 1936;
constexpr int NCLS  = 14;

// fc1 GEMM padded dims (split bf16: A'=[Ahi|Ahi|Alo], B'=[Bhi|Blo|Bhi])
constexpr int KSEC  = 7168;
constexpr int KP    = 3 * KSEC;       // 21504
constexpr int NPAD  = 2048;
constexpr int KT    = KP / 32;        // 672

// ---------------------------------------------------------------------------
// Scratch
// ---------------------------------------------------------------------------
__device__ __align__(16) float g_xt[(size_t)BSZ * CCH * TLEN];
__device__ __align__(16) float g_h[(size_t)BSZ * HID];
__device__ __align__(16) __nv_bfloat16 g_A2[(size_t)BSZ * KP];
__device__ __align__(16) __nv_bfloat16 g_B2[(size_t)NPAD * KP];

// ---------------------------------------------------------------------------
// PTX helpers (sm_80+ portable)
// ---------------------------------------------------------------------------
__device__ __forceinline__ uint32_t smem_to_u32(const void* p) {
    uint32_t a;
    asm("{ .reg .u64 t; cvta.to.shared.u64 t, %1; cvt.u32.u64 %0, t; }" : "=r"(a) : "l"(p));
    return a;
}
__device__ __forceinline__ void cp16(uint32_t dst, const void* src) {
    asm volatile("cp.async.cg.shared.global [%0], [%1], 16;" :: "r"(dst), "l"(src));
}
#define CP_COMMIT() asm volatile("cp.async.commit_group;" ::: "memory")
#define CP_WAIT2()  asm volatile("cp.async.wait_group 2;" ::: "memory")

__device__ __forceinline__ void ldsm_x4(uint32_t* r, uint32_t addr) {
    asm volatile("ldmatrix.sync.aligned.m8n8.x4.shared.b16 {%0,%1,%2,%3}, [%4];"
                 : "=r"(r[0]), "=r"(r[1]), "=r"(r[2]), "=r"(r[3]) : "r"(addr));
}
__device__ __forceinline__ void mma16816(float* d, const uint32_t* a,
                                         uint32_t b0, uint32_t b1) {
    asm volatile(
        "mma.sync.aligned.m16n8k16.row.col.f32.bf16.bf16.f32 "
        "{%0,%1,%2,%3}, {%4,%5,%6,%7}, {%8,%9}, {%0,%1,%2,%3};"
        : "+f"(d[0]), "+f"(d[1]), "+f"(d[2]), "+f"(d[3])
        : "r"(a[0]), "r"(a[1]), "r"(a[2]), "r"(a[3]), "r"(b0), "r"(b1));
}

// ---------------------------------------------------------------------------
// Transpose: x (B, T, C) -> g_xt (B, C, T)
// ---------------------------------------------------------------------------
__global__ void __launch_bounds__(256) transpose_kernel(const float* __restrict__ x) {
    __shared__ float s[TLEN * CCH];
    const int b = blockIdx.x;
    const float* src = x + (size_t)b * TLEN * CCH;
    for (int i = threadIdx.x; i < TLEN * CCH; i += 256) s[i] = src[i];
    __syncthreads();
    float* dst = g_xt + (size_t)b * CCH * TLEN;
    for (int i = threadIdx.x; i < TLEN * CCH; i += 256) {
        int c = i / TLEN, t = i - c * TLEN;
        dst[i] = s[t * CCH + c];
    }
}

// ---------------------------------------------------------------------------
// Split-write helper: emit one feature value as bf16 hi/lo into g_A2 sections
// A' layout per row m: [hi | hi | lo] at col, col+KSEC, col+2*KSEC
// ---------------------------------------------------------------------------
__device__ __forceinline__ void emit_feat(__nv_bfloat16* arow, int col, float v) {
    __nv_bfloat16 h = __float2bfloat16(v);
    __nv_bfloat16 l = __float2bfloat16(v - __bfloat162float(h));
    arow[col]            = h;
    arow[col + KSEC]     = h;
    arow[col + 2 * KSEC] = l;
}

// ---------------------------------------------------------------------------
// Feature extraction (fused bf16 split output). One 64-thread block per (b,c).
// ---------------------------------------------------------------------------
template<int K, int PAD>
__device__ __forceinline__ void run_branch(
    const float* xsp, float* hs, float* z1,
    const float* ws,  const float* bs,
    const float* wi1, const float* bi1,
    const float* wi2, const float* bi2,
    __nv_bfloat16* arow, int col0, int tid)
{
    {   // stage 1: shared conv 1->8 (96), relu, pool2 -> hs rows of 48
        // 6-output windows: thread (o, q) computes u = 6q..6q+5 from v[0..10+K]
        const int o = tid >> 3, q = tid & 7;
        float wreg[K];
        #pragma unroll
        for (int k = 0; k < K; k++) wreg[k] = ws[o * K + k];
        const float bo = bs[o];
        float v[11 + K];
        const int t0 = 12 * q - PAD;
        #pragma unroll
        for (int j = 0; j < 11 + K; j++) v[j] = xsp[t0 + j];
        float* hrow = hs + o * 56 + 4;
        #pragma unroll
        for (int d = 0; d < 6; d++) {
            float a0 = bo, a1 = bo;
            #pragma unroll
            for (int k = 0; k < K; k++) {
                a0 = fmaf(v[2 * d + k],     wreg[k], a0);
                a1 = fmaf(v[2 * d + 1 + k], wreg[k], a1);
            }
            hrow[6 * q + d] = 0.5f * (fmaxf(a0, 0.f) + fmaxf(a1, 0.f));
        }
    }
    __syncthreads();
    {   // stage 2: grouped conv 8->4 (48), relu, pool2 -> z1 rows of 24
        const int j = tid >> 4, g = tid & 15;
        const float bj = bi1[j];
        const float* wbase = wi1 + j * 8 * K;
        for (int uu = g; uu < 24; uu += 16) {
            const int t0 = 2 * uu - PAD;
            float a0 = bj, a1 = bj;
            #pragma unroll
            for (int i = 0; i < 8; i++) {
                const float* hrow = hs + i * 56 + 4 + t0;
                const float* wr = wbase + i * K;
                float v[K + 1];
                #pragma unroll
                for (int jj = 0; jj <= K; jj++) v[jj] = hrow[jj];
                #pragma unroll
                for (int k = 0; k < K; k++) {
                    float w = wr[k];
                    a0 = fmaf(v[k],     w, a0);
                    a1 = fmaf(v[k + 1], w, a1);
                }
            }
            z1[j * 32 + 4 + uu] = 0.5f * (fmaxf(a0, 0.f) + fmaxf(a1, 0.f));
        }
    }
    __syncthreads();
    {   // stage 3: grouped conv 4->4 (24), relu, pool2 -> 12 outputs, emit bf16
        const int j = tid >> 4, g = tid & 15;
        if (g < 12) {
            const int uu = g;
            const int t0 = 2 * uu - PAD;
            float a0 = bi2[j], a1 = bi2[j];
            #pragma unroll
            for (int i = 0; i < 4; i++) {
                const float* zrow = z1 + i * 32 + 4 + t0;
                const float* wr = wi2 + (j * 4 + i) * K;
                float v[K + 1];
                #pragma unroll
                for (int jj = 0; jj <= K; jj++) v[jj] = zrow[jj];
                #pragma unroll
                for (int k = 0; k < K; k++) {
                    float w = wr[k];
                    a0 = fmaf(v[k],     w, a0);
                    a1 = fmaf(v[k + 1], w, a1);
                }
            }
            emit_feat(arow, col0 + j * 12 + uu,
                      0.5f * (fmaxf(a0, 0.f) + fmaxf(a1, 0.f)));
        }
    }
    __syncthreads();
}

__global__ void __launch_bounds__(64) feat_kernel(
    const float* __restrict__ w_hs, const float* __restrict__ b_hs,
    const float* __restrict__ w_ls, const float* __restrict__ b_ls,
    const float* __restrict__ w_hi1, const float* __restrict__ b_hi1,
    const float* __restrict__ w_hi2, const float* __restrict__ b_hi2,
    const float* __restrict__ w_li1, const float* __restrict__ b_li1,
    const float* __restrict__ w_li2, const float* __restrict__ b_li2)
{
    const int c = blockIdx.x;
    const int b = blockIdx.y;
    const int tid = threadIdx.x;

    __shared__ float xs[104];
    __shared__ float hs[8 * 56];
    __shared__ float z1[4 * 32];
    __shared__ float sw_h[8 * 7],       sw_l[8 * 3];
    __shared__ float swi1_h[4 * 8 * 7], swi2_h[4 * 4 * 7];
    __shared__ float swi1_l[4 * 8 * 3], swi2_l[4 * 4 * 3];
    __shared__ float sb_h[8], sb_l[8];
    __shared__ float sbi1_h[4], sbi2_h[4], sbi1_l[4], sbi2_l[4];

    for (int i = tid; i < 8 * 56; i += 64) hs[i] = 0.f;
    for (int i = tid; i < 4 * 32; i += 64) z1[i] = 0.f;
    if (tid < 4) { xs[tid] = 0.f; xs[100 + tid] = 0.f; }

    const float* xrow = g_xt + ((size_t)b * CCH + c) * TLEN;
    for (int i = tid; i < 96; i += 64) xs[4 + i] = xrow[i];
    for (int i = tid; i < 56; i += 64) sw_h[i] = w_hs[i];
    if (tid < 24)                      sw_l[tid] = w_ls[tid];
    if (tid < 8) { sb_h[tid] = b_hs[tid]; sb_l[tid] = b_ls[tid]; }
    for (int i = tid; i < 224; i += 64) swi1_h[i] = w_hi1[c * 224 + i];
    for (int i = tid; i < 112; i += 64) swi2_h[i] = w_hi2[c * 112 + i];
    for (int i = tid; i < 96;  i += 64) swi1_l[i] = w_li1[c * 96 + i];
    if (tid < 48)                       swi2_l[tid] = w_li2[c * 48 + tid];
    if (tid < 4) {
        sbi1_h[tid] = b_hi1[c * 4 + tid];
        sbi2_h[tid] = b_hi2[c * 4 + tid];
        sbi1_l[tid] = b_li1[c * 4 + tid];
        sbi2_l[tid] = b_li2[c * 4 + tid];
    }
    __syncthreads();

    __nv_bfloat16* arow = g_A2 + (size_t)b * KP;
    const int col0 = c * 108;
    const float* xsp = xs + 4;

    if (tid < 12) {   // slot 0: mean of 8
        float s = 0.f;
        #pragma unroll
        for (int k = 0; k < 8; k++) s += xsp[tid * 8 + k];
        emit_feat(arow, col0 + tid, s * 0.125f);
    }
    // K-pad zeroing (cols 7128..7168 of each section), done by c==65 blocks
    if (c == CCH - 1 && tid < 40) {
        const __nv_bfloat16 z = __float2bfloat16(0.f);
        arow[FIN + tid]            = z;
        arow[FIN + tid + KSEC]     = z;
        arow[FIN + tid + 2 * KSEC] = z;
    }

    run_branch<3, 1>(xsp, hs, z1, sw_l, sb_l, swi1_l, sbi1_l, swi2_l, sbi2_l, arow, col0 + 12, tid);
    run_branch<7, 3>(xsp, hs, z1, sw_h, sb_h, swi1_h, sbi1_h, swi2_h, sbi2_h, arow, col0 + 60, tid);
}

// ---------------------------------------------------------------------------
// Weight conversion: B' = [Bhi | Blo | Bhi]
// ---------------------------------------------------------------------------
__global__ void __launch_bounds__(256) convB_kernel(const float* __restrict__ w1) {
    const size_t idx = (size_t)blockIdx.x * 256 + threadIdx.x;   // 2048*896
    const int n  = (int)(idx / 896);
    const int kb = (int)(idx % 896);
    const int k0 = kb * 8;
    float v[8];
    if (n < HID && kb < 891) {
        float4 a = *(const float4*)(w1 + (size_t)n * FIN + k0);
        float4 b = *(const float4*)(w1 + (size_t)n * FIN + k0 + 4);
        v[0]=a.x; v[1]=a.y; v[2]=a.z; v[3]=a.w; v[4]=b.x; v[5]=b.y; v[6]=b.z; v[7]=b.w;
    } else {
        #pragma unroll
        for (int i = 0; i < 8; i++) v[i] = 0.f;
    }
    __align__(16) __nv_bfloat16 hi[8], lo[8];
    #pragma unroll
    for (int i = 0; i < 8; i++) {
        __nv_bfloat16 h = __float2bfloat16(v[i]);
        hi[i] = h;
        lo[i] = __float2bfloat16(v[i] - __bfloat162float(h));
    }
    __nv_bfloat16* dst = g_B2 + (size_t)n * KP + k0;
    *(uint4*)(dst)            = *(uint4*)hi;
    *(uint4*)(dst + KSEC)     = *(uint4*)lo;
    *(uint4*)(dst + 2 * KSEC) = *(uint4*)hi;
}

// ---------------------------------------------------------------------------
// fc1 GEMM (HMMA bf16): 256x128 tile, grid 16x8 = 128 blocks (1 wave).
// 8 warps as 4(m) x 2(n), warp tile 64x64, acc[4][8][4].
// SMEM/stage: A 256x32 (16KB) + B 128x32 (8KB) = 24KB; 4 stages = 96KB.
// ---------------------------------------------------------------------------
constexpr int GSTAGES = 4;
constexpr int STAGE_BYTES = 24576;
constexpr int GSMEM_BYTES = GSTAGES * STAGE_BYTES;   // 96 KB

__global__ void __launch_bounds__(256) gemm_kernel(const float* __restrict__ bias) {
    extern __shared__ char smem[];
    const uint32_t smem_u32 = smem_to_u32(smem);
    const int tid  = threadIdx.x;
    const int wid  = tid >> 5;
    const int lane = tid & 31;
    const int bm = blockIdx.y * 256;
    const int bn = blockIdx.x * 128;

    const int warp_m = wid & 3;          // 4 -> 64 rows each
    const int warp_n = wid >> 2;         // 2 -> 64 cols each

    // cp.async: per thread 4 A-chunks + 2 B-chunks of 16B
    const int lcu  = tid & 3;
    const int lrow = tid >> 2;           // 0..63
    const __nv_bfloat16* srcA[4];
    const __nv_bfloat16* srcB[2];
    uint32_t dstA[4], dstB[2];
    #pragma unroll
    for (int i = 0; i < 4; i++) {
        const int r = lrow + 64 * i;
        srcA[i] = g_A2 + (size_t)(bm + r) * KP + lcu * 8;
        dstA[i] = r * 64 + (uint32_t)((lcu ^ ((r >> 1) & 3)) << 4);
    }
    #pragma unroll
    for (int i = 0; i < 2; i++) {
        const int r = lrow + 64 * i;
        srcB[i] = g_B2 + (size_t)(bn + r) * KP + lcu * 8;
        dstB[i] = 16384 + r * 64 + (uint32_t)((lcu ^ ((r >> 1) & 3)) << 4);
    }

    // ldmatrix offsets
    const int g8 = lane >> 3;
    const int l8 = lane & 7;
    uint32_t aoff[8];                    // [mt][ks]
    #pragma unroll
    for (int mt = 0; mt < 4; mt++) {
        const int mrow = warp_m * 64 + mt * 16 + (g8 & 1) * 8 + l8;
        const int s = (mrow >> 1) & 3;
        #pragma unroll
        for (int ks = 0; ks < 2; ks++) {
            const int cu = 2 * ks + (g8 >> 1);
            aoff[mt * 2 + ks] = mrow * 64 + ((cu ^ s) << 4);
        }
    }
    uint32_t boff[8];                    // [p][ks]
    #pragma unroll
    for (int p = 0; p < 4; p++) {
        const int nrow = warp_n * 64 + p * 16 + (g8 >> 1) * 8 + l8;
        const int s = (nrow >> 1) & 3;
        #pragma unroll
        for (int ks = 0; ks < 2; ks++) {
            const int cu = 2 * ks + (g8 & 1);
            boff[p * 2 + ks] = 16384 + nrow * 64 + ((cu ^ s) << 4);
        }
    }

    float acc[4][8][4];
    #pragma unroll
    for (int mt = 0; mt < 4; mt++)
        #pragma unroll
        for (int nt = 0; nt < 8; nt++)
            #pragma unroll
            for (int e = 0; e < 4; e++) acc[mt][nt][e] = 0.f;

    // prologue: 3 stages
    #pragma unroll
    for (int kt = 0; kt < GSTAGES - 1; kt++) {
        const uint32_t sb = smem_u32 + kt * STAGE_BYTES;
        #pragma unroll
        for (int i = 0; i < 4; i++) cp16(sb + dstA[i], srcA[i] + (size_t)kt * 32);
        #pragma unroll
        for (int i = 0; i < 2; i++) cp16(sb + dstB[i], srcB[i] + (size_t)kt * 32);
        CP_COMMIT();
    }

    for (int kt = 0; kt < KT; kt++) {
        CP_WAIT2();
        __syncthreads();

        const int knext = kt + GSTAGES - 1;
        if (knext < KT) {
            const uint32_t sb = smem_u32 + (knext & 3) * STAGE_BYTES;
            #pragma unroll
            for (int i = 0; i < 4; i++) cp16(sb + dstA[i], srcA[i] + (size_t)knext * 32);
            #pragma unroll
            for (int i = 0; i < 2; i++) cp16(sb + dstB[i], srcB[i] + (size_t)knext * 32);
        }
        CP_COMMIT();

        const uint32_t sb = smem_u32 + (kt & 3) * STAGE_BYTES;
        #pragma unroll
        for (int ks = 0; ks < 2; ks++) {
            uint32_t afr[4][4], bfr[4][4];
            #pragma unroll
            for (int mt = 0; mt < 4; mt++) ldsm_x4(afr[mt], sb + aoff[mt * 2 + ks]);
            #pragma unroll
            for (int p = 0; p < 4; p++)    ldsm_x4(bfr[p],  sb + boff[p * 2 + ks]);
            #pragma unroll
            for (int mt = 0; mt < 4; mt++)
                #pragma unroll
                for (int nt = 0; nt < 8; nt++)
                    mma16816(acc[mt][nt], afr[mt],
                             bfr[nt >> 1][(nt & 1) * 2],
                             bfr[nt >> 1][(nt & 1) * 2 + 1]);
        }
    }

    // epilogue: bias + relu -> g_h
    const int qrow = lane >> 2;
    const int qcol = (lane & 3) * 2;
    #pragma unroll
    for (int mt = 0; mt < 4; mt++) {
        #pragma unroll
        for (int nt = 0; nt < 8; nt++) {
            const int n = bn + warp_n * 64 + nt * 8 + qcol;
            if (n >= HID) continue;
            const float b0 = bias[n], b1 = bias[n + 1];
            #pragma unroll
            for (int half = 0; half < 2; half++) {
                const int m = bm + warp_m * 64 + mt * 16 + qrow + half * 8;
                float* o = g_h + (size_t)m * HID + n;
                o[0] = fmaxf(acc[mt][nt][half * 2 + 0] + b0, 0.f);
                o[1] = fmaxf(acc[mt][nt][half * 2 + 1] + b1, 0.f);
            }
        }
    }
}

// ---------------------------------------------------------------------------
// fc2: warp-per-row, 14 outputs in registers, g_h read exactly once.
// ---------------------------------------------------------------------------
__global__ void __launch_bounds__(256) fc2_kernel(
    const float* __restrict__ w2, const float* __restrict__ b2,
    float* __restrict__ out)
{
    const int wid  = threadIdx.x >> 5;
    const int lane = threadIdx.x & 31;
    const int m = blockIdx.x * 8 + wid;

    const float* hrow = g_h + (size_t)m * HID;
    float acc[NCLS];
    #pragma unroll
    for (int n = 0; n < NCLS; n++) acc[n] = 0.f;

    for (int k = lane; k < HID; k += 32) {
        const float h = hrow[k];
        #pragma unroll
        for (int n = 0; n < NCLS; n++)
            acc[n] = fmaf(h, w2[n * HID + k], acc[n]);
    }
    #pragma unroll
    for (int n = 0; n < NCLS; n++)
        #pragma unroll
        for (int off = 16; off > 0; off >>= 1)
            acc[n] += __shfl_down_sync(0xffffffffu, acc[n], off);
    if (lane == 0) {
        #pragma unroll
        for (int n = 0; n < NCLS; n++)
            out[m * NCLS + n] = acc[n] + b2[n];
    }
}

// ---------------------------------------------------------------------------
// Entry
// ---------------------------------------------------------------------------
extern "C" void kernel_launch(void* const* d_in, const int* in_sizes, int n_in,
                              void* d_out, int out_size)
{
    const float* x     = (const float*)d_in[0];
    const float* w_hs  = (const float*)d_in[1];
    const float* b_hs  = (const float*)d_in[2];
    const float* w_ls  = (const float*)d_in[3];
    const float* b_ls  = (const float*)d_in[4];
    const float* w_hi1 = (const float*)d_in[5];
    const float* b_hi1 = (const float*)d_in[6];
    const float* w_hi2 = (const float*)d_in[7];
    const float* b_hi2 = (const float*)d_in[8];
    const float* w_li1 = (const float*)d_in[9];
    const float* b_li1 = (const float*)d_in[10];
    const float* w_li2 = (const float*)d_in[11];
    const float* b_li2 = (const float*)d_in[12];
    const float* w_fc1 = (const float*)d_in[13];
    const float* b_fc1 = (const float*)d_in[14];
    const float* w_fc2 = (const float*)d_in[15];
    const float* b_fc2 = (const float*)d_in[16];
    float* out = (float*)d_out;

    static bool attr_set = false;
    if (!attr_set) {
        cudaFuncSetAttribute(gemm_kernel, cudaFuncAttributeMaxDynamicSharedMemorySize,
                             GSMEM_BYTES);
        attr_set = true;
    }

    transpose_kernel<<<BSZ, 256>>>(x);
    convB_kernel<<<(NPAD * 896) / 256, 256>>>(w_fc1);
    feat_kernel<<<dim3(CCH, BSZ), 64>>>(w_hs, b_hs, w_ls, b_ls,
                                        w_hi1, b_hi1, w_hi2, b_hi2,
                                        w_li1, b_li1, w_li2, b_li2);
    gemm_kernel<<<dim3(16, 8), 256, GSMEM_BYTES>>>(b_fc1);
    fc2_kernel<<<BSZ / 8, 256>>>(w_fc2, b_fc2, out);
}

// round 6
// speedup vs baseline: 1.1275x; 1.1275x over previous
#include <cuda_runtime.h>
#include <cuda_bf16.h>
#include <cstdint>

// ---------------------------------------------------------------------------
// Problem constants
// ---------------------------------------------------------------------------
constexpr int CCH   = 66;
constexpr int TLEN  = 96;
constexpr int BSZ   = 2048;
constexpr int FIN   = 9 * CCH * 12;   // 7128
constexpr int HID   = 1936;
constexpr int NCLS  = 14;

// fc1 GEMM padded dims (split bf16: A'=[Ahi|Ahi|Alo], B'=[Bhi|Blo|Bhi])
constexpr int KSEC  = 7168;
constexpr int KP    = 3 * KSEC;       // 21504
constexpr int NPAD  = 2048;
constexpr int KT    = KP / 32;        // 672

// ---------------------------------------------------------------------------
// Scratch
// ---------------------------------------------------------------------------
__device__ __align__(16) float g_xt[(size_t)BSZ * CCH * TLEN];
__device__ __align__(16) float g_h[(size_t)BSZ * HID];
__device__ __align__(16) __nv_bfloat16 g_A2[(size_t)BSZ * KP];
__device__ __align__(16) __nv_bfloat16 g_B2[(size_t)NPAD * KP];

// ---------------------------------------------------------------------------
// PTX helpers (sm_80+ portable)
// ---------------------------------------------------------------------------
__device__ __forceinline__ uint32_t smem_to_u32(const void* p) {
    uint32_t a;
    asm("{ .reg .u64 t; cvta.to.shared.u64 t, %1; cvt.u32.u64 %0, t; }" : "=r"(a) : "l"(p));
    return a;
}
__device__ __forceinline__ void cp16(uint32_t dst, const void* src) {
    asm volatile("cp.async.cg.shared.global [%0], [%1], 16;" :: "r"(dst), "l"(src));
}
#define CP_COMMIT() asm volatile("cp.async.commit_group;" ::: "memory")
#define CP_WAIT2()  asm volatile("cp.async.wait_group 2;" ::: "memory")

__device__ __forceinline__ void ldsm_x4(uint32_t* r, uint32_t addr) {
    asm volatile("ldmatrix.sync.aligned.m8n8.x4.shared.b16 {%0,%1,%2,%3}, [%4];"
                 : "=r"(r[0]), "=r"(r[1]), "=r"(r[2]), "=r"(r[3]) : "r"(addr));
}
__device__ __forceinline__ void mma16816(float* d, const uint32_t* a,
                                         uint32_t b0, uint32_t b1) {
    asm volatile(
        "mma.sync.aligned.m16n8k16.row.col.f32.bf16.bf16.f32 "
        "{%0,%1,%2,%3}, {%4,%5,%6,%7}, {%8,%9}, {%0,%1,%2,%3};"
        : "+f"(d[0]), "+f"(d[1]), "+f"(d[2]), "+f"(d[3])
        : "r"(a[0]), "r"(a[1]), "r"(a[2]), "r"(a[3]), "r"(b0), "r"(b1));
}
__device__ __forceinline__ uint32_t pack_bf2(__nv_bfloat16 a, __nv_bfloat16 b) {
    __nv_bfloat162 t(a, b);
    return *(uint32_t*)&t;
}

// ---------------------------------------------------------------------------
// Transpose: x (B, T, C) -> g_xt (B, C, T)
// ---------------------------------------------------------------------------
__global__ void __launch_bounds__(256) transpose_kernel(const float* __restrict__ x) {
    __shared__ float s[TLEN * CCH];
    const int b = blockIdx.x;
    const float* src = x + (size_t)b * TLEN * CCH;
    for (int i = threadIdx.x; i < TLEN * CCH; i += 256) s[i] = src[i];
    __syncthreads();
    float* dst = g_xt + (size_t)b * CCH * TLEN;
    for (int i = threadIdx.x; i < TLEN * CCH; i += 256) {
        int c = i / TLEN, t = i - c * TLEN;
        dst[i] = s[t * CCH + c];
    }
}

// ---------------------------------------------------------------------------
// Feature extraction. One 64-thread block per (b, c).
// Features staged in SMEM; packed bf16x2 u32 emission at the end.
// ---------------------------------------------------------------------------
template<int K, int PAD>
__device__ __forceinline__ void run_branch(
    const float* xsp, float* hs, float* z1,
    const float* ws,  const float* bs,
    const float* wi1, const float* bi1,
    const float* wi2, const float* bi2,
    float* feat_s, int slot0, int tid)
{
    {   // stage 1: shared conv 1->8 (96), relu, pool2 -> hs rows of 48
        const int o = tid >> 3, q = tid & 7;
        float wreg[K];
        #pragma unroll
        for (int k = 0; k < K; k++) wreg[k] = ws[o * K + k];
        const float bo = bs[o];
        float v[11 + K];
        const int t0 = 12 * q - PAD;
        #pragma unroll
        for (int j = 0; j < 11 + K; j++) v[j] = xsp[t0 + j];
        float* hrow = hs + o * 56 + 4;
        #pragma unroll
        for (int d = 0; d < 6; d++) {
            float a0 = bo, a1 = bo;
            #pragma unroll
            for (int k = 0; k < K; k++) {
                a0 = fmaf(v[2 * d + k],     wreg[k], a0);
                a1 = fmaf(v[2 * d + 1 + k], wreg[k], a1);
            }
            hrow[6 * q + d] = 0.5f * (fmaxf(a0, 0.f) + fmaxf(a1, 0.f));
        }
    }
    __syncthreads();
    {   // stage 2: grouped conv 8->4 (48), relu, pool2 -> z1 rows of 24
        const int j = tid >> 4, g = tid & 15;
        const float bj = bi1[j];
        const float* wbase = wi1 + j * 8 * K;
        for (int uu = g; uu < 24; uu += 16) {
            const int t0 = 2 * uu - PAD;
            float a0 = bj, a1 = bj;
            #pragma unroll
            for (int i = 0; i < 8; i++) {
                const float* hrow = hs + i * 56 + 4 + t0;
                const float* wr = wbase + i * K;
                float v[K + 1];
                #pragma unroll
                for (int jj = 0; jj <= K; jj++) v[jj] = hrow[jj];
                #pragma unroll
                for (int k = 0; k < K; k++) {
                    float w = wr[k];
                    a0 = fmaf(v[k],     w, a0);
                    a1 = fmaf(v[k + 1], w, a1);
                }
            }
            z1[j * 32 + 4 + uu] = 0.5f * (fmaxf(a0, 0.f) + fmaxf(a1, 0.f));
        }
    }
    __syncthreads();
    {   // stage 3: grouped conv 4->4 (24), relu, pool2 -> 12 outputs
        const int j = tid >> 4, g = tid & 15;
        if (g < 12) {
            const int uu = g;
            const int t0 = 2 * uu - PAD;
            float a0 = bi2[j], a1 = bi2[j];
            #pragma unroll
            for (int i = 0; i < 4; i++) {
                const float* zrow = z1 + i * 32 + 4 + t0;
                const float* wr = wi2 + (j * 4 + i) * K;
                float v[K + 1];
                #pragma unroll
                for (int jj = 0; jj <= K; jj++) v[jj] = zrow[jj];
                #pragma unroll
                for (int k = 0; k < K; k++) {
                    float w = wr[k];
                    a0 = fmaf(v[k],     w, a0);
                    a1 = fmaf(v[k + 1], w, a1);
                }
            }
            feat_s[(slot0 + j) * 12 + uu] = 0.5f * (fmaxf(a0, 0.f) + fmaxf(a1, 0.f));
        }
    }
    __syncthreads();
}

__global__ void __launch_bounds__(64) feat_kernel(
    const float* __restrict__ w_hs, const float* __restrict__ b_hs,
    const float* __restrict__ w_ls, const float* __restrict__ b_ls,
    const float* __restrict__ w_hi1, const float* __restrict__ b_hi1,
    const float* __restrict__ w_hi2, const float* __restrict__ b_hi2,
    const float* __restrict__ w_li1, const float* __restrict__ b_li1,
    const float* __restrict__ w_li2, const float* __restrict__ b_li2)
{
    const int c = blockIdx.x;
    const int b = blockIdx.y;
    const int tid = threadIdx.x;

    __shared__ float xs[104];
    __shared__ float hs[8 * 56];
    __shared__ float z1[4 * 32];
    __shared__ float feat_s[108];
    __shared__ float sw_h[8 * 7],       sw_l[8 * 3];
    __shared__ float swi1_h[4 * 8 * 7], swi2_h[4 * 4 * 7];
    __shared__ float swi1_l[4 * 8 * 3], swi2_l[4 * 4 * 3];
    __shared__ float sb_h[8], sb_l[8];
    __shared__ float sbi1_h[4], sbi2_h[4], sbi1_l[4], sbi2_l[4];

    for (int i = tid; i < 8 * 56; i += 64) hs[i] = 0.f;
    for (int i = tid; i < 4 * 32; i += 64) z1[i] = 0.f;
    if (tid < 4) { xs[tid] = 0.f; xs[100 + tid] = 0.f; }

    const float* xrow = g_xt + ((size_t)b * CCH + c) * TLEN;
    for (int i = tid; i < 96; i += 64) xs[4 + i] = xrow[i];
    for (int i = tid; i < 56; i += 64) sw_h[i] = w_hs[i];
    if (tid < 24)                      sw_l[tid] = w_ls[tid];
    if (tid < 8) { sb_h[tid] = b_hs[tid]; sb_l[tid] = b_ls[tid]; }
    for (int i = tid; i < 224; i += 64) swi1_h[i] = w_hi1[c * 224 + i];
    for (int i = tid; i < 112; i += 64) swi2_h[i] = w_hi2[c * 112 + i];
    for (int i = tid; i < 96;  i += 64) swi1_l[i] = w_li1[c * 96 + i];
    if (tid < 48)                       swi2_l[tid] = w_li2[c * 48 + tid];
    if (tid < 4) {
        sbi1_h[tid] = b_hi1[c * 4 + tid];
        sbi2_h[tid] = b_hi2[c * 4 + tid];
        sbi1_l[tid] = b_li1[c * 4 + tid];
        sbi2_l[tid] = b_li2[c * 4 + tid];
    }
    __syncthreads();

    const float* xsp = xs + 4;

    if (tid < 12) {   // slot 0: mean of 8
        float s = 0.f;
        #pragma unroll
        for (int k = 0; k < 8; k++) s += xsp[tid * 8 + k];
        feat_s[tid] = s * 0.125f;
    }

    run_branch<3, 1>(xsp, hs, z1, sw_l, sb_l, swi1_l, sbi1_l, swi2_l, sbi2_l, feat_s, 1, tid);
    run_branch<7, 3>(xsp, hs, z1, sw_h, sb_h, swi1_h, sbi1_h, swi2_h, sbi2_h, feat_s, 5, tid);

    // emit: packed bf16x2 u32 stores, 54 per section
    uint32_t* a32 = (uint32_t*)(g_A2 + (size_t)b * KP);
    if (tid < 54) {
        const float v0 = feat_s[2 * tid], v1 = feat_s[2 * tid + 1];
        const __nv_bfloat16 h0 = __float2bfloat16(v0);
        const __nv_bfloat16 h1 = __float2bfloat16(v1);
        const __nv_bfloat16 l0 = __float2bfloat16(v0 - __bfloat162float(h0));
        const __nv_bfloat16 l1 = __float2bfloat16(v1 - __bfloat162float(h1));
        const uint32_t hp = pack_bf2(h0, h1);
        const uint32_t lp = pack_bf2(l0, l1);
        const int base = c * 54 + tid;
        a32[base]            = hp;
        a32[base + KSEC / 2] = hp;
        a32[base + KSEC]     = lp;
    }
    // K-pad zeroing (cols 7128..7167 of each section) by c==65 blocks
    if (c == CCH - 1 && tid < 20) {
        const int base = FIN / 2 + tid;
        a32[base]            = 0u;
        a32[base + KSEC / 2] = 0u;
        a32[base + KSEC]     = 0u;
    }
}

// ---------------------------------------------------------------------------
// Weight conversion: B' = [Bhi | Blo | Bhi]
// ---------------------------------------------------------------------------
__global__ void __launch_bounds__(256) convB_kernel(const float* __restrict__ w1) {
    const size_t idx = (size_t)blockIdx.x * 256 + threadIdx.x;   // 2048*896
    const int n  = (int)(idx / 896);
    const int kb = (int)(idx % 896);
    const int k0 = kb * 8;
    float v[8];
    if (n < HID && kb < 891) {
        float4 a = *(const float4*)(w1 + (size_t)n * FIN + k0);
        float4 b = *(const float4*)(w1 + (size_t)n * FIN + k0 + 4);
        v[0]=a.x; v[1]=a.y; v[2]=a.z; v[3]=a.w; v[4]=b.x; v[5]=b.y; v[6]=b.z; v[7]=b.w;
    } else {
        #pragma unroll
        for (int i = 0; i < 8; i++) v[i] = 0.f;
    }
    __align__(16) __nv_bfloat16 hi[8], lo[8];
    #pragma unroll
    for (int i = 0; i < 8; i++) {
        __nv_bfloat16 h = __float2bfloat16(v[i]);
        hi[i] = h;
        lo[i] = __float2bfloat16(v[i] - __bfloat162float(h));
    }
    __nv_bfloat16* dst = g_B2 + (size_t)n * KP + k0;
    *(uint4*)(dst)            = *(uint4*)hi;
    *(uint4*)(dst + KSEC)     = *(uint4*)lo;
    *(uint4*)(dst + 2 * KSEC) = *(uint4*)hi;
}

// ---------------------------------------------------------------------------
// fc1 GEMM (HMMA bf16): 256x128 tile, 512 threads / 16 warps (4m x 4n),
// warp tile 64x32, 4-stage cp.async. grid 16x8 = 128 blocks.
// SMEM/stage: A 256x32 (16KB) + B 128x32 (8KB) = 24KB; 4 stages = 96KB.
// ---------------------------------------------------------------------------
constexpr int GSTAGES = 4;
constexpr int STAGE_BYTES = 24576;
constexpr int GSMEM_BYTES = GSTAGES * STAGE_BYTES;   // 96 KB

__global__ void __launch_bounds__(512) gemm_kernel(const float* __restrict__ bias) {
    extern __shared__ char smem[];
    const uint32_t smem_u32 = smem_to_u32(smem);
    const int tid  = threadIdx.x;
    const int wid  = tid >> 5;
    const int lane = tid & 31;
    const int bm = blockIdx.y * 256;
    const int bn = blockIdx.x * 128;

    const int warp_m = wid & 3;          // 4 -> 64 rows each
    const int warp_n = wid >> 2;         // 4 -> 32 cols each

    // cp.async: per thread 2 A-chunks + 1 B-chunk of 16B
    const int lcu  = tid & 3;
    const int lrow = tid >> 2;           // 0..127
    const __nv_bfloat16* srcA[2];
    const __nv_bfloat16* srcB;
    uint32_t dstA[2], dstB;
    #pragma unroll
    for (int i = 0; i < 2; i++) {
        const int r = lrow + 128 * i;
        srcA[i] = g_A2 + (size_t)(bm + r) * KP + lcu * 8;
        dstA[i] = r * 64 + (uint32_t)((lcu ^ ((r >> 1) & 3)) << 4);
    }
    srcB = g_B2 + (size_t)(bn + lrow) * KP + lcu * 8;
    dstB = 16384 + lrow * 64 + (uint32_t)((lcu ^ ((lrow >> 1) & 3)) << 4);

    // ldmatrix offsets
    const int g8 = lane >> 3;
    const int l8 = lane & 7;
    uint32_t aoff[8];                    // [mt][ks], mt 0..3
    #pragma unroll
    for (int mt = 0; mt < 4; mt++) {
        const int mrow = warp_m * 64 + mt * 16 + (g8 & 1) * 8 + l8;
        const int s = (mrow >> 1) & 3;
        #pragma unroll
        for (int ks = 0; ks < 2; ks++) {
            const int cu = 2 * ks + (g8 >> 1);
            aoff[mt * 2 + ks] = mrow * 64 + ((cu ^ s) << 4);
        }
    }
    uint32_t boff[4];                    // [p][ks], p 0..1 (16 cols each)
    #pragma unroll
    for (int p = 0; p < 2; p++) {
        const int nrow = warp_n * 32 + p * 16 + (g8 >> 1) * 8 + l8;
        const int s = (nrow >> 1) & 3;
        #pragma unroll
        for (int ks = 0; ks < 2; ks++) {
            const int cu = 2 * ks + (g8 & 1);
            boff[p * 2 + ks] = 16384 + nrow * 64 + ((cu ^ s) << 4);
        }
    }

    float acc[4][4][4];
    #pragma unroll
    for (int mt = 0; mt < 4; mt++)
        #pragma unroll
        for (int nt = 0; nt < 4; nt++)
            #pragma unroll
            for (int e = 0; e < 4; e++) acc[mt][nt][e] = 0.f;

    // prologue: 3 stages
    #pragma unroll
    for (int kt = 0; kt < GSTAGES - 1; kt++) {
        const uint32_t sb = smem_u32 + kt * STAGE_BYTES;
        #pragma unroll
        for (int i = 0; i < 2; i++) cp16(sb + dstA[i], srcA[i] + (size_t)kt * 32);
        cp16(sb + dstB, srcB + (size_t)kt * 32);
        CP_COMMIT();
    }

    for (int kt = 0; kt < KT; kt++) {
        CP_WAIT2();
        __syncthreads();

        const int knext = kt + GSTAGES - 1;
        if (knext < KT) {
            const uint32_t sb = smem_u32 + (knext & 3) * STAGE_BYTES;
            #pragma unroll
            for (int i = 0; i < 2; i++) cp16(sb + dstA[i], srcA[i] + (size_t)knext * 32);
            cp16(sb + dstB, srcB + (size_t)knext * 32);
        }
        CP_COMMIT();

        const uint32_t sb = smem_u32 + (kt & 3) * STAGE_BYTES;
        #pragma unroll
        for (int ks = 0; ks < 2; ks++) {
            uint32_t afr[4][4], bfr[2][4];
            #pragma unroll
            for (int mt = 0; mt < 4; mt++) ldsm_x4(afr[mt], sb + aoff[mt * 2 + ks]);
            #pragma unroll
            for (int p = 0; p < 2; p++)    ldsm_x4(bfr[p],  sb + boff[p * 2 + ks]);
            #pragma unroll
            for (int mt = 0; mt < 4; mt++)
                #pragma unroll
                for (int nt = 0; nt < 4; nt++)
                    mma16816(acc[mt][nt], afr[mt],
                             bfr[nt >> 1][(nt & 1) * 2],
                             bfr[nt >> 1][(nt & 1) * 2 + 1]);
        }
    }

    // epilogue: bias + relu -> g_h
    const int qrow = lane >> 2;
    const int qcol = (lane & 3) * 2;
    #pragma unroll
    for (int mt = 0; mt < 4; mt++) {
        #pragma unroll
        for (int nt = 0; nt < 4; nt++) {
            const int n = bn + warp_n * 32 + nt * 8 + qcol;
            if (n >= HID) continue;
            const float b0 = bias[n], b1 = bias[n + 1];
            #pragma unroll
            for (int half = 0; half < 2; half++) {
                const int m = bm + warp_m * 64 + mt * 16 + qrow + half * 8;
                float* o = g_h + (size_t)m * HID + n;
                o[0] = fmaxf(acc[mt][nt][half * 2 + 0] + b0, 0.f);
                o[1] = fmaxf(acc[mt][nt][half * 2 + 1] + b1, 0.f);
            }
        }
    }
}

// ---------------------------------------------------------------------------
// fc2: warp-per-row, 14 outputs in registers, g_h read exactly once.
// ---------------------------------------------------------------------------
__global__ void __launch_bounds__(256) fc2_kernel(
    const float* __restrict__ w2, const float* __restrict__ b2,
    float* __restrict__ out)
{
    const int wid  = threadIdx.x >> 5;
    const int lane = threadIdx.x & 31;
    const int m = blockIdx.x * 8 + wid;

    const float* hrow = g_h + (size_t)m * HID;
    float acc[NCLS];
    #pragma unroll
    for (int n = 0; n < NCLS; n++) acc[n] = 0.f;

    for (int k = lane; k < HID; k += 32) {
        const float h = hrow[k];
        #pragma unroll
        for (int n = 0; n < NCLS; n++)
            acc[n] = fmaf(h, w2[n * HID + k], acc[n]);
    }
    #pragma unroll
    for (int n = 0; n < NCLS; n++)
        #pragma unroll
        for (int off = 16; off > 0; off >>= 1)
            acc[n] += __shfl_down_sync(0xffffffffu, acc[n], off);
    if (lane == 0) {
        #pragma unroll
        for (int n = 0; n < NCLS; n++)
            out[m * NCLS + n] = acc[n] + b2[n];
    }
}

// ---------------------------------------------------------------------------
// Entry
// ---------------------------------------------------------------------------
extern "C" void kernel_launch(void* const* d_in, const int* in_sizes, int n_in,
                              void* d_out, int out_size)
{
    const float* x     = (const float*)d_in[0];
    const float* w_hs  = (const float*)d_in[1];
    const float* b_hs  = (const float*)d_in[2];
    const float* w_ls  = (const float*)d_in[3];
    const float* b_ls  = (const float*)d_in[4];
    const float* w_hi1 = (const float*)d_in[5];
    const float* b_hi1 = (const float*)d_in[6];
    const float* w_hi2 = (const float*)d_in[7];
    const float* b_hi2 = (const float*)d_in[8];
    const float* w_li1 = (const float*)d_in[9];
    const float* b_li1 = (const float*)d_in[10];
    const float* w_li2 = (const float*)d_in[11];
    const float* b_li2 = (const float*)d_in[12];
    const float* w_fc1 = (const float*)d_in[13];
    const float* b_fc1 = (const float*)d_in[14];
    const float* w_fc2 = (const float*)d_in[15];
    const float* b_fc2 = (const float*)d_in[16];
    float* out = (float*)d_out;

    static bool attr_set = false;
    if (!attr_set) {
        cudaFuncSetAttribute(gemm_kernel, cudaFuncAttributeMaxDynamicSharedMemorySize,
                             GSMEM_BYTES);
        attr_set = true;
    }

    transpose_kernel<<<BSZ, 256>>>(x);
    convB_kernel<<<(NPAD * 896) / 256, 256>>>(w_fc1);
    feat_kernel<<<dim3(CCH, BSZ), 64>>>(w_hs, b_hs, w_ls, b_ls,
                                        w_hi1, b_hi1, w_hi2, b_hi2,
                                        w_li1, b_li1, w_li2, b_li2);
    gemm_kernel<<<dim3(16, 8), 512, GSMEM_BYTES>>>(b_fc1);
    fc2_kernel<<<BSZ / 8, 256>>>(w_fc2, b_fc2, out);
}